// round 10
// baseline (speedup 1.0000x reference)
#include <cuda_runtime.h>
#include <math_constants.h>

// Morphological opening (10x10 min then 10x10 max, SAME pad lo=4/hi=5),
// NHWC [16,512,512,8] f32. Two symmetric passes via transposed global
// scratch. vs round 9: van Herk prefix loops restructured so tail loads are
// unconditional (clamped addresses + select) and the loop has no break ->
// ptxas batches the loads instead of serializing 8 x mem-latency per task.
//   K1 erosion:  V-min fused w/ coalesced load -> smem -> H-min -> S[b][x][y][h]
//   K2 dilation: X-max fused w/ coalesced load of S (off-image = -inf = pad)
//                -> smem -> Y-max -> out (original layout).

#define H_  512
#define W_  512
#define NT  256

#define NCF  146          // (64+9)*2 fused (coord, float4-half) columns
#define SMEM_F4 (32 * NCF)           // 4672
#define SMEM_BYTES (SMEM_F4 * 16)    // 74752 -> 3 blocks/SM (224.25KB + reserve)

// Transposed eroded scratch: S[b][x][y][h], f4 units.
__device__ float4 g_scratch[16 * 512 * 512 * 2];

__device__ __forceinline__ float4 min4(float4 a, float4 b) {
    return make_float4(fminf(a.x,b.x), fminf(a.y,b.y), fminf(a.z,b.z), fminf(a.w,b.w));
}
__device__ __forceinline__ float4 max4(float4 a, float4 b) {
    return make_float4(fmaxf(a.x,b.x), fmaxf(a.y,b.y), fmaxf(a.z,b.z), fmaxf(a.w,b.w));
}
__device__ __forceinline__ int clampi(int v, int lo, int hi) {
    return min(max(v, lo), hi);
}

// ============================ K1: erosion =================================
// Block: 32 y-outputs x 64 x-outputs x 8 channels.
__global__ __launch_bounds__(NT, 3)
void erode_kernel(const float4* __restrict__ in4) {
    extern __shared__ float4 B[];     // B[e][cF]: e in [0,32), cF in [0,146)
    const int b   = blockIdx.z;
    const int gy0 = blockIdx.y * 32;
    const int gx0 = blockIdx.x * 64;
    const int tid = threadIdx.x;
    const float4 INF4 = make_float4(CUDART_INF_F, CUDART_INF_F, CUDART_INF_F, CUDART_INF_F);

    const size_t inBase = (size_t)b * H_ * W_ * 2;

    // ---- Stage 1: vertical min fused with coalesced load. 146 x 4 = 584. ----
    #pragma unroll 1
    for (int i = tid; i < NCF * 4; i += NT) {
        int cF = i % NCF, seg = i / NCF;
        int e0 = seg * 9;
        int n  = (seg == 3) ? 5 : 9;             // 9+9+9+5 = 32
        int gx = gx0 + (cF >> 1) - 4;
        bool colOK = ((unsigned)gx < W_);
        int gxc = clampi(gx, 0, W_ - 1);
        // clamped base: always a valid address; select INF when off-image
        const float4* src = in4 + inBase + (size_t)gxc * 2 + (cF & 1);
        int yBase = gy0 + e0 - 4;

        float4 x[10];
        #pragma unroll
        for (int t = 0; t < 10; t++) {
            int gy  = yBase + t;
            bool ok = colOK && ((unsigned)gy < H_);
            float4 v = src[(size_t)clampi(gy, 0, H_ - 1) * (W_ * 2)];
            x[t] = ok ? v : INF4;
        }
        #pragma unroll
        for (int j = 8; j >= 0; j--) x[j] = min4(x[j], x[j+1]);
        // batched tail loads (independent of pr chain)
        float4 y[8];
        #pragma unroll
        for (int j = 0; j < 8; j++) {
            int gy  = yBase + 10 + j;
            bool ok = colOK && ((unsigned)gy < H_);
            float4 v = src[(size_t)clampi(gy, 0, H_ - 1) * (W_ * 2)];
            y[j] = ok ? v : INF4;
        }
        float4 pr = x[9];
        float4* q = B + e0 * NCF + cF;
        q[0] = x[0];
        #pragma unroll
        for (int j = 1; j < 9; j++) {
            pr = min4(pr, y[j - 1]);
            if (j < n) q[j * NCF] = min4(x[j], pr);
        }
    }
    __syncthreads();

    // ---- Stage 2: horizontal min, write transposed scratch (coalesced). ----
    #pragma unroll 1
    for (int i = tid; i < 512; i += NT) {
        int h   = i & 1;
        int e   = (i >> 1) & 31;
        int seg = i >> 6;              // 0..7
        int c0  = seg * 9;
        int n   = (seg == 7) ? 1 : 9;
        const float4* row = B + e * NCF + h;
        float4 x[10];
        #pragma unroll
        for (int t = 0; t < 10; t++) x[t] = row[(c0 + t) * 2];
        #pragma unroll
        for (int j = 8; j >= 0; j--) x[j] = min4(x[j], x[j+1]);
        float4 y[8];
        #pragma unroll
        for (int j = 0; j < 8; j++)
            y[j] = row[clampi(c0 + 10 + j, 0, 72) * 2];   // clamp: seg 7 tail
        float4 pr = x[9];
        float4* q = g_scratch + (size_t)b * (H_ * W_ * 2)
                  + ((size_t)(gx0 + c0) * H_ + (gy0 + e)) * 2 + h;
        q[0] = x[0];
        #pragma unroll
        for (int j = 1; j < 9; j++) {
            pr = min4(pr, y[j - 1]);
            if (j < n) q[(size_t)j * (H_ * 2)] = min4(x[j], pr);
        }
    }
}

// ============================ K2: dilation ================================
// Block: 32 x-outputs x 64 y-outputs x 8 channels. Mirror of K1 on S.
__global__ __launch_bounds__(NT, 3)
void dilate_kernel(float4* __restrict__ out4) {
    extern __shared__ float4 B[];     // B[e][yF]: e = x-idx in [0,32), yF in [0,146)
    const int b   = blockIdx.z;
    const int gx0 = blockIdx.y * 32;
    const int gy0 = blockIdx.x * 64;
    const int tid = threadIdx.x;
    const float4 NINF4 = make_float4(-CUDART_INF_F, -CUDART_INF_F, -CUDART_INF_F, -CUDART_INF_F);

    const size_t sBase = (size_t)b * (H_ * W_ * 2);

    // ---- Stage 1: max along x fused with coalesced load of S. 146x4=584. ----
    // Off-image (x or y) contributes -inf == dilation SAME padding.
    #pragma unroll 1
    for (int i = tid; i < NCF * 4; i += NT) {
        int yF = i % NCF, seg = i / NCF;
        int e0 = seg * 9;
        int n  = (seg == 3) ? 5 : 9;
        int gy = gy0 + (yF >> 1) - 4;
        bool yOK = ((unsigned)gy < H_);
        int gyc = clampi(gy, 0, H_ - 1);
        const float4* src = g_scratch + sBase + (size_t)gyc * 2 + (yF & 1);
        int xBase = gx0 + e0 - 4;

        float4 x[10];
        #pragma unroll
        for (int t = 0; t < 10; t++) {
            int gx  = xBase + t;
            bool ok = yOK && ((unsigned)gx < W_);
            float4 v = src[(size_t)clampi(gx, 0, W_ - 1) * (H_ * 2)];
            x[t] = ok ? v : NINF4;
        }
        #pragma unroll
        for (int j = 8; j >= 0; j--) x[j] = max4(x[j], x[j+1]);
        float4 y[8];
        #pragma unroll
        for (int j = 0; j < 8; j++) {
            int gx  = xBase + 10 + j;
            bool ok = yOK && ((unsigned)gx < W_);
            float4 v = src[(size_t)clampi(gx, 0, W_ - 1) * (H_ * 2)];
            y[j] = ok ? v : NINF4;
        }
        float4 pr = x[9];
        float4* q = B + e0 * NCF + yF;
        q[0] = x[0];
        #pragma unroll
        for (int j = 1; j < 9; j++) {
            pr = max4(pr, y[j - 1]);
            if (j < n) q[j * NCF] = max4(x[j], pr);
        }
    }
    __syncthreads();

    // ---- Stage 2: max along y, write output (coalesced, original layout). ----
    #pragma unroll 1
    for (int i = tid; i < 512; i += NT) {
        int h   = i & 1;
        int e   = (i >> 1) & 31;
        int seg = i >> 6;
        int c0  = seg * 9;
        int n   = (seg == 7) ? 1 : 9;
        const float4* row = B + e * NCF + h;
        float4 x[10];
        #pragma unroll
        for (int t = 0; t < 10; t++) x[t] = row[(c0 + t) * 2];
        #pragma unroll
        for (int j = 8; j >= 0; j--) x[j] = max4(x[j], x[j+1]);
        float4 y[8];
        #pragma unroll
        for (int j = 0; j < 8; j++)
            y[j] = row[clampi(c0 + 10 + j, 0, 72) * 2];
        float4 pr = x[9];
        float4* q = out4 + (size_t)b * (H_ * W_ * 2)
                  + ((size_t)(gy0 + c0) * W_ + (gx0 + e)) * 2 + h;
        q[0] = x[0];
        #pragma unroll
        for (int j = 1; j < 9; j++) {
            pr = max4(pr, y[j - 1]);
            if (j < n) q[(size_t)j * (W_ * 2)] = max4(x[j], pr);
        }
    }
}

extern "C" void kernel_launch(void* const* d_in, const int* in_sizes, int n_in,
                              void* d_out, int out_size) {
    const float4* in  = (const float4*)d_in[0];
    float4* out = (float4*)d_out;

    cudaFuncSetAttribute(erode_kernel,
                         cudaFuncAttributeMaxDynamicSharedMemorySize, SMEM_BYTES);
    cudaFuncSetAttribute(dilate_kernel,
                         cudaFuncAttributeMaxDynamicSharedMemorySize, SMEM_BYTES);

    dim3 g1(W_ / 64, H_ / 32, 16);   // x-tiles, y-tiles, batch
    dim3 g2(H_ / 64, W_ / 32, 16);   // y-tiles, x-tiles, batch
    erode_kernel <<<g1, NT, SMEM_BYTES>>>(in);
    dilate_kernel<<<g2, NT, SMEM_BYTES>>>(out);
}